// round 14
// baseline (speedup 1.0000x reference)
#include <cuda_runtime.h>
#include <cuda_bf16.h>
#include <math.h>
#include <stdint.h>

// ---- problem constants ----
#define VV 100000
#define EE 400000
#define GG 200
#define NFEAT 74
#define NEFEAT 12

// ---- scratch (activations bf16) ----
__device__ __nv_bfloat16  g_hvb [VV * GG];
__device__ __nv_bfloat16  g_he1b[EE * GG];
__device__ __nv_bfloat16  g_cgb [VV * GG];
__device__ __nv_bfloat16  g_hvpb[VV * GG];
__device__ __nv_bfloat16  g_cb  [VV * GG];
__device__ __nv_bfloat16  g_gib [VV * 3 * GG];
__device__ __nv_bfloat16  g_ghb [VV * 3 * GG];
__device__ uint32_t       g_wb[430000];
__device__ float          g_mask[VV];
__device__ float          g_d0[VV];
__device__ float          g_d1[VV];
__device__ float          g_logit[EE];
__device__ float          g_gsum[8192];
__device__ int            g_rowptr[VV + 1];
__device__ int            g_cursor[VV];
__device__ int            g_csr[EE];

// ---- helpers ----
__device__ __forceinline__ float lreluf(float x) { return x > 0.f ? x : 0.01f * x; }
__device__ __forceinline__ float sigmoidf_(float x) { return 1.f / (1.f + expf(-x)); }
__device__ __forceinline__ float warp_sum(float v) {
    #pragma unroll
    for (int o = 16; o; o >>= 1) v += __shfl_down_sync(0xffffffffu, v, o);
    return v;
}
__device__ __forceinline__ float warp_allmax(float v) {
    #pragma unroll
    for (int o = 16; o; o >>= 1) v = fmaxf(v, __shfl_xor_sync(0xffffffffu, v, o));
    return v;
}
__device__ __forceinline__ uint32_t packbf(float lo, float hi) {
    __nv_bfloat162 p = __floats2bfloat162_rn(lo, hi);
    return *reinterpret_cast<uint32_t*>(&p);
}
__device__ __forceinline__ void unpackbf(uint32_t u, float& lo, float& hi) {
    __nv_bfloat162 p = *reinterpret_cast<__nv_bfloat162*>(&u);
    lo = __bfloat162float(p.x);
    hi = __bfloat162float(p.y);
}
__device__ __forceinline__ void cp_async16(uint32_t saddr, const void* g, int bytes) {
    asm volatile("cp.async.cg.shared.global [%0], [%1], 16, %2;"
                 :: "r"(saddr), "l"(g), "r"(bytes));
}
__device__ __forceinline__ void cp_commit() { asm volatile("cp.async.commit_group;"); }
template<int NN>
__device__ __forceinline__ void cp_wait() { asm volatile("cp.async.wait_group %0;" :: "n"(NN)); }

// ---- init ----
__global__ void init_kernel(int* rowptr, int nrp, float* logit, int E,
                            float* gsum, int NG,
                            const float* __restrict__ nf, float* __restrict__ mask, int V) {
    int i = blockIdx.x * blockDim.x + threadIdx.x;
    if (i < nrp) rowptr[i] = 0;
    if (i < E) logit[i] = 0.f;
    if (i < NG) gsum[i] = 0.f;
    if (i < V) {
        const float* r = nf + (long)i * NFEAT;
        float s = r[NFEAT - 4] + r[NFEAT - 3] + r[NFEAT - 2] + r[NFEAT - 1];
        mask[i] = 1.f / (s * (1.f - r[0])) - 1.f;
    }
}

// ---- batched weight conversion ----
struct ConvJobs {
    const float* W[9];
    uint32_t* B[9];
    int K[9], N[9];
    int njobs;
};
__global__ void convw_all_kernel(ConvJobs J) {
    int j = blockIdx.y;
    if (j >= J.njobs) return;
    const float* W = J.W[j];
    uint32_t* Bt = J.B[j];
    int K = J.K[j], N = J.N[j];
    int K2 = K >> 1;
    int tot = N * K2;
    for (int idx = blockIdx.x * blockDim.x + threadIdx.x; idx < tot;
         idx += gridDim.x * blockDim.x) {
        int n = idx / K2, k2 = idx - n * K2;
        Bt[idx] = packbf(W[(long)(2 * k2) * N + n], W[(long)(2 * k2 + 1) * N + n]);
    }
}

// ---- CSR build ----
__global__ void hist_kernel(const int* __restrict__ dst, int* __restrict__ rowptr, int E) {
    int e = blockIdx.x * blockDim.x + threadIdx.x;
    if (e < E) atomicAdd(&rowptr[dst[e] + 1], 1);
}
__global__ void scan_kernel(int* __restrict__ p, int n) {
    __shared__ int tsum[1024];
    int tid = threadIdx.x;
    int chunk = (n + 1023) / 1024;
    int s0 = tid * chunk, s1 = min(s0 + chunk, n);
    int sum = 0;
    for (int i = s0; i < s1; i++) sum += p[i];
    tsum[tid] = sum;
    __syncthreads();
    int val = tsum[tid];
    #pragma unroll
    for (int o = 1; o < 1024; o <<= 1) {
        int other = (tid >= o) ? tsum[tid - o] : 0;
        __syncthreads();
        val += other;
        tsum[tid] = val;
        __syncthreads();
    }
    int offset = (tid > 0) ? tsum[tid - 1] : 0;
    int run = offset;
    for (int i = s0; i < s1; i++) { run += p[i]; p[i] = run; }
}
__global__ void copy_i_kernel(const int* __restrict__ a, int* __restrict__ b, int n) {
    int i = blockIdx.x * blockDim.x + threadIdx.x;
    if (i < n) b[i] = a[i];
}
__global__ void csr_scatter_kernel(const int* __restrict__ dst, int* __restrict__ cursor,
                                   int* __restrict__ csr, int E) {
    int e = blockIdx.x * blockDim.x + threadIdx.x;
    if (e >= E) return;
    int pos = atomicAdd(&cursor[dst[e]], 1);
    csr[pos] = e;
}

#define BM 128
#define BN 128
#define BK 32
#define SA 20
#define GSTG 3
#define GTSZ (128 * SA)

struct GemmJobs {
    const __nv_bfloat16* A[2];
    const uint32_t* Bt[2];
    const float* bias[2];
    __nv_bfloat16* C[2];
};

// ============================================================
// Streaming bf16 GEMM, occupancy 3, z-batched (2 jobs max).
// EPI: 0=store(+bias), 1=elu(+bias)
// ============================================================
template<int EPI>
__global__ __launch_bounds__(128, 3)
void mma_bf16_kernel(GemmJobs J, int M, int N, int K)
{
    extern __shared__ uint32_t smdyn[];
    uint32_t* Asm = smdyn;
    uint32_t* Bsm = smdyn + GSTG * GTSZ;

    const __nv_bfloat16* __restrict__ A = J.A[blockIdx.z];
    const uint32_t* __restrict__ Bt = J.Bt[blockIdx.z];
    const float* __restrict__ bias = J.bias[blockIdx.z];
    __nv_bfloat16* __restrict__ C = J.C[blockIdx.z];

    const int tid = threadIdx.x;
    const int row0 = blockIdx.y * BM;
    const int col0 = blockIdx.x * BN;
    const int warp = tid >> 5, lane = tid & 31;
    const int wm = (warp & 1) * 64, wn = (warp >> 1) * 64;
    const int gq = lane >> 2, tq = lane & 3;
    const int K2 = K >> 1;
    const int nk = (K + BK - 1) / BK;

    const uint32_t sA0 = (uint32_t)__cvta_generic_to_shared(Asm);
    const uint32_t sB0 = (uint32_t)__cvta_generic_to_shared(Bsm);

    float acc[4][8][4] = {};

    auto issue = [&](int kt, int s) {
        int k2t = kt * 16;
        #pragma unroll
        for (int i = 0; i < 4; i++) {
            int idx = i * 128 + tid;
            int r = idx >> 2, seg = idx & 3;
            int k2g = k2t + seg * 4;
            {
                int gr = row0 + r;
                bool ok = (gr < M) && (k2g < K2);
                int bytes = ok ? min(16, (K2 - k2g) * 4) : 0;
                const void* gp = ok ? (const void*)(A + (long)gr * K + 2 * k2g)
                                    : (const void*)A;
                cp_async16(sA0 + (s * GTSZ + r * SA + seg * 4) * 4, gp, bytes);
            }
            {
                int gn = col0 + r;
                bool ok = (gn < N) && (k2g < K2);
                int bytes = ok ? min(16, (K2 - k2g) * 4) : 0;
                const void* gp = ok ? (const void*)(Bt + (long)gn * K2 + k2g)
                                    : (const void*)Bt;
                cp_async16(sB0 + (s * GTSZ + r * SA + seg * 4) * 4, gp, bytes);
            }
        }
        cp_commit();
    };

    const int rowA  = (lane & 7) + (lane & 8);
    const int kaddA = (lane & 16) >> 2;
    const int rowB  = (lane & 7) + ((lane & 16) >> 1);
    const int kaddB = (lane & 8) >> 1;

    auto compute = [&](int s) {
        #pragma unroll
        for (int ks = 0; ks < 2; ks++) {
            uint32_t af[4][4], bf[8][2];
            #pragma unroll
            for (int mt = 0; mt < 4; mt++) {
                uint32_t addr = sA0 + (s * GTSZ + (wm + mt * 16 + rowA) * SA + 8 * ks + kaddA) * 4;
                asm volatile("ldmatrix.sync.aligned.m8n8.x4.shared.b16 {%0,%1,%2,%3}, [%4];"
                    : "=r"(af[mt][0]), "=r"(af[mt][1]), "=r"(af[mt][2]), "=r"(af[mt][3])
                    : "r"(addr));
            }
            #pragma unroll
            for (int np = 0; np < 4; np++) {
                uint32_t addr = sB0 + (s * GTSZ + (wn + np * 16 + rowB) * SA + 8 * ks + kaddB) * 4;
                asm volatile("ldmatrix.sync.aligned.m8n8.x4.shared.b16 {%0,%1,%2,%3}, [%4];"
                    : "=r"(bf[2 * np][0]), "=r"(bf[2 * np][1]),
                      "=r"(bf[2 * np + 1][0]), "=r"(bf[2 * np + 1][1])
                    : "r"(addr));
            }
            #pragma unroll
            for (int mt = 0; mt < 4; mt++)
                #pragma unroll
                for (int nt = 0; nt < 8; nt++) {
                    asm volatile(
                        "mma.sync.aligned.m16n8k16.row.col.f32.bf16.bf16.f32 "
                        "{%0,%1,%2,%3},{%4,%5,%6,%7},{%8,%9},{%0,%1,%2,%3};"
                        : "+f"(acc[mt][nt][0]), "+f"(acc[mt][nt][1]),
                          "+f"(acc[mt][nt][2]), "+f"(acc[mt][nt][3])
                        : "r"(af[mt][0]), "r"(af[mt][1]), "r"(af[mt][2]), "r"(af[mt][3]),
                          "r"(bf[nt][0]), "r"(bf[nt][1]));
                }
        }
    };

    issue(0, 0);
    if (nk > 1) issue(1, 1);
    for (int kt = 0; kt < nk; kt++) {
        if (kt < nk - 1) cp_wait<1>(); else cp_wait<0>();
        __syncthreads();
        if (kt + 2 < nk) issue(kt + 2, (kt + 2) % GSTG);
        compute(kt % GSTG);
    }

    #pragma unroll
    for (int mt = 0; mt < 4; mt++) {
        int r0 = row0 + wm + mt * 16 + gq;
        int r1 = r0 + 8;
        #pragma unroll
        for (int nt = 0; nt < 8; nt++) {
            int cn = col0 + wn + nt * 8 + tq * 2;
            if (cn >= N) continue;
            float b0 = bias[cn], b1 = bias[cn + 1];
            float v00 = acc[mt][nt][0] + b0, v01 = acc[mt][nt][1] + b1;
            float v10 = acc[mt][nt][2] + b0, v11 = acc[mt][nt][3] + b1;
            if (EPI == 1) {
                v00 = v00 > 0.f ? v00 : expm1f(v00);
                v01 = v01 > 0.f ? v01 : expm1f(v01);
                v10 = v10 > 0.f ? v10 : expm1f(v10);
                v11 = v11 > 0.f ? v11 : expm1f(v11);
            }
            if (r0 < M) *(uint32_t*)&C[(long)r0 * N + cn] = packbf(v00, v01);
            if (r1 < M) *(uint32_t*)&C[(long)r1 * N + cn] = packbf(v10, v11);
        }
    }
}

// ============================================================
// Small-K GEMM (fp32 inputs), bf16 lrelu store.
// AM: 0=direct, 2=concat. LOGIT: atomicAdd dot(lrelu_row, wlog) into logit[row].
// ============================================================
#define SB2 20
template<int AM, int LOGIT>
__global__ __launch_bounds__(256, 2)
void mma_smallk_kernel(const float* __restrict__ A, int lda,
                       const float* __restrict__ B,
                       const float* __restrict__ bias,
                       __nv_bfloat16* __restrict__ Cb,
                       int M, int N, int K,
                       const float* __restrict__ nodef, const float* __restrict__ edgef,
                       const int* __restrict__ src,
                       const float* __restrict__ wlog, float* __restrict__ logit)
{
    __shared__ uint32_t As[2][BM * SA];
    __shared__ uint32_t Bs[2][BN * SB2];

    const int tid = threadIdx.x;
    const int row0 = blockIdx.y * BM;
    const int col0 = blockIdx.x * BN;
    const int warp = tid >> 5, lane = tid & 31;
    const int gq = lane >> 2, tq = lane & 3;
    const int wm = (warp & 1) * 64;
    const int wn = (warp >> 1) * 32;
    const int nk = (K + BK - 1) / BK;

    float acc[4][4][4] = {};
    uint32_t ra[8], rb[8];

    auto loadA = [&](int k0) {
        #pragma unroll
        for (int i = 0; i < 8; i++) {
            int e = i * 256 + tid;
            int r = e >> 4, k2 = e & 15;
            int gr = row0 + r, gk = k0 + 2 * k2;
            float v0 = 0.f, v1 = 0.f;
            if (gr < M && gk < K) {
                if (AM == 2) {
                    if (gk < NFEAT) {
                        int s = src[gr];
                        const float* p = &nodef[(long)s * NFEAT + gk];
                        v0 = p[0]; v1 = p[1];
                    } else {
                        const float* p = &edgef[(long)gr * NEFEAT + (gk - NFEAT)];
                        v0 = p[0]; v1 = p[1];
                    }
                } else {
                    const float2 p = *(const float2*)&A[(long)gr * lda + gk];
                    v0 = p.x; v1 = p.y;
                }
            }
            ra[i] = packbf(v0, v1);
        }
    };
    auto loadB = [&](int k0) {
        #pragma unroll
        for (int i = 0; i < 8; i++) {
            int e = i * 256 + tid;
            int k2 = e >> 7, n = e & 127;
            int gk = k0 + 2 * k2, gn = col0 + n;
            float v0 = 0.f, v1 = 0.f;
            if (gk < K && gn < N) {
                v0 = B[(long)gk * N + gn];
                v1 = B[(long)(gk + 1) * N + gn];
            }
            rb[i] = packbf(v0, v1);
        }
    };
    auto storeA = [&](int buf) {
        #pragma unroll
        for (int i = 0; i < 8; i++) {
            int e = i * 256 + tid;
            As[buf][(e >> 4) * SA + (e & 15)] = ra[i];
        }
    };
    auto storeB = [&](int buf) {
        #pragma unroll
        for (int i = 0; i < 8; i++) {
            int e = i * 256 + tid;
            Bs[buf][(e & 127) * SB2 + (e >> 7)] = rb[i];
        }
    };
    auto compute = [&](int buf) {
        #pragma unroll
        for (int ks = 0; ks < 2; ks++) {
            uint32_t af[4][4], bf[4][2];
            #pragma unroll
            for (int mt = 0; mt < 4; mt++) {
                int r = wm + mt * 16 + gq;
                int kb = ks * 8 + tq;
                af[mt][0] = As[buf][(r    ) * SA + kb    ];
                af[mt][1] = As[buf][(r + 8) * SA + kb    ];
                af[mt][2] = As[buf][(r    ) * SA + kb + 4];
                af[mt][3] = As[buf][(r + 8) * SA + kb + 4];
            }
            #pragma unroll
            for (int nt = 0; nt < 4; nt++) {
                int n = wn + nt * 8 + gq;
                int kb = ks * 8 + tq;
                bf[nt][0] = Bs[buf][n * SB2 + kb    ];
                bf[nt][1] = Bs[buf][n * SB2 + kb + 4];
            }
            #pragma unroll
            for (int mt = 0; mt < 4; mt++)
                #pragma unroll
                for (int nt = 0; nt < 4; nt++) {
                    asm volatile(
                        "mma.sync.aligned.m16n8k16.row.col.f32.bf16.bf16.f32 "
                        "{%0,%1,%2,%3},{%4,%5,%6,%7},{%8,%9},{%0,%1,%2,%3};"
                        : "+f"(acc[mt][nt][0]), "+f"(acc[mt][nt][1]),
                          "+f"(acc[mt][nt][2]), "+f"(acc[mt][nt][3])
                        : "r"(af[mt][0]), "r"(af[mt][1]), "r"(af[mt][2]), "r"(af[mt][3]),
                          "r"(bf[nt][0]), "r"(bf[nt][1]));
                }
        }
    };

    loadA(0); loadB(0);
    storeA(0); storeB(0);
    __syncthreads();
    for (int kt = 0; kt < nk; kt++) {
        int buf = kt & 1;
        if (kt + 1 < nk) { loadA((kt + 1) * BK); loadB((kt + 1) * BK); }
        compute(buf);
        if (kt + 1 < nk) {
            __syncthreads();
            storeA(buf ^ 1); storeB(buf ^ 1);
            __syncthreads();
        }
    }

    float rsum[4][2] = {};
    #pragma unroll
    for (int mt = 0; mt < 4; mt++) {
        int rr[2] = { row0 + wm + mt * 16 + gq, row0 + wm + mt * 16 + gq + 8 };
        #pragma unroll
        for (int nt = 0; nt < 4; nt++) {
            int cn = col0 + wn + nt * 8 + tq * 2;
            if (cn >= N) continue;
            float b0 = bias[cn], b1 = bias[cn + 1];
            float w0 = 0.f, w1 = 0.f;
            if (LOGIT) { w0 = wlog[cn]; w1 = wlog[cn + 1]; }
            #pragma unroll
            for (int h = 0; h < 2; h++) {
                if (rr[h] >= M) continue;
                float v0 = lreluf(acc[mt][nt][2 * h] + b0);
                float v1 = lreluf(acc[mt][nt][2 * h + 1] + b1);
                *(uint32_t*)&Cb[(long)rr[h] * N + cn] = packbf(v0, v1);
                if (LOGIT) rsum[mt][h] += v0 * w0 + v1 * w1;
            }
        }
    }
    if (LOGIT) {
        #pragma unroll
        for (int mt = 0; mt < 4; mt++) {
            #pragma unroll
            for (int h = 0; h < 2; h++) {
                float s = rsum[mt][h];
                s += __shfl_xor_sync(0xffffffffu, s, 1);
                s += __shfl_xor_sync(0xffffffffu, s, 2);
                int row = row0 + wm + mt * 16 + gq + 8 * h;
                if (tq == 0 && row < M) atomicAdd(&logit[row], s);
            }
        }
    }
}

// ---- per-node dot (bf16 X) ----
__global__ void node_dots_kernel(const __nv_bfloat16* __restrict__ X,
                                 const float* __restrict__ w0,
                                 float* __restrict__ out0, int V)
{
    int node = (blockIdx.x * blockDim.x + threadIdx.x) >> 5;
    int lane = threadIdx.x & 31;
    if (node >= V) return;
    const uint32_t* x = (const uint32_t*)(X + (long)node * GG);
    float s0 = 0.f;
    #pragma unroll
    for (int k = 0; k < 4; k++) {
        int j2 = lane + 32 * k;
        if (j2 < GG / 2) {
            float lo, hi; unpackbf(x[j2], lo, hi);
            s0 += lo * w0[2 * j2] + hi * w0[2 * j2 + 1];
        }
    }
    s0 = warp_sum(s0);
    if (lane == 0) out0[node] = s0;
}

// ---- finalize context logit ----
__global__ void logit_fin_kernel(float* __restrict__ logit, const float* __restrict__ d0,
                                 const int* __restrict__ dst, const float* __restrict__ b, int E)
{
    int e = blockIdx.x * blockDim.x + threadIdx.x;
    if (e >= E) return;
    logit[e] = lreluf(logit[e] + d0[dst[e]] + b[0]);
}

// ============================================================
// Fused attention softmax + gather (warp per node).
// ============================================================
template<int MODE>
__global__ void att_gather_kernel(const __nv_bfloat16* __restrict__ X,
                                  const float* __restrict__ logit,
                                  const float* __restrict__ d0, const float* __restrict__ d1,
                                  const int* __restrict__ srcmap, const float* __restrict__ b,
                                  const int* __restrict__ rowptr, const int* __restrict__ csr,
                                  __nv_bfloat16* __restrict__ outb, int V)
{
    int node = (blockIdx.x * blockDim.x + threadIdx.x) >> 5;
    int lane = threadIdx.x & 31;
    if (node >= V) return;
    int s0 = rowptr[node], s1 = rowptr[node + 1];
    uint32_t* cd = (uint32_t*)(outb + (long)node * GG);
    if (s0 == s1) {
        #pragma unroll
        for (int k = 0; k < 4; k++) {
            int j2 = lane + 32 * k;
            if (j2 < GG / 2) cd[j2] = 0u;
        }
        return;
    }
    float d0v = 0.f, bv = 0.f;
    if (MODE == 1) { d0v = d0[node]; bv = b[0]; }
    float m = -1e30f;
    for (int i = s0 + lane; i < s1; i += 32) {
        int e = csr[i];
        float l = (MODE == 1) ? lreluf(d0v + d1[srcmap[e]] + bv) : logit[e];
        m = fmaxf(m, l);
    }
    m = warp_allmax(m);
    float s = 0.f;
    float accx[4] = {0.f, 0.f, 0.f, 0.f};
    float accy[4] = {0.f, 0.f, 0.f, 0.f};
    for (int i = s0; i < s1; i++) {
        int e = csr[i];
        long row;
        float l;
        if (MODE == 1) {
            int sr = srcmap[e];
            l = lreluf(d0v + d1[sr] + bv);
            row = sr;
        } else {
            l = logit[e];
            row = e;
        }
        float w = expf(l - m);
        s += w;
        const uint32_t* x = (const uint32_t*)(X + row * GG);
        #pragma unroll
        for (int k = 0; k < 4; k++) {
            int j2 = lane + 32 * k;
            if (j2 < GG / 2) {
                float lo, hi; unpackbf(x[j2], lo, hi);
                accx[k] = fmaf(w, lo, accx[k]);
                accy[k] = fmaf(w, hi, accy[k]);
            }
        }
    }
    float inv = 1.f / s;
    #pragma unroll
    for (int k = 0; k < 4; k++) {
        int j2 = lane + 32 * k;
        if (j2 < GG / 2) {
            float lo = accx[k] * inv, hi = accy[k] * inv;
            if (MODE == 1) {
                lo = lo > 0.f ? lo : expm1f(lo);
                hi = hi > 0.f ? hi : expm1f(hi);
            }
            cd[j2] = packbf(lo, hi);
        }
    }
}

// ---- fused GRU gates + (next-layer dots | pKa readout) ----
__global__ void gru_gates_fused(const __nv_bfloat16* __restrict__ gib,
                                const __nv_bfloat16* __restrict__ ghb,
                                __nv_bfloat16* __restrict__ hb,
                                const float* __restrict__ w0, const float* __restrict__ w1,
                                float* __restrict__ d0, float* __restrict__ d1,
                                const float* __restrict__ predb, const float* __restrict__ mask,
                                const int* __restrict__ gids, float* __restrict__ out_atom,
                                float* __restrict__ gsum, int V, int mode)
{
    int v = (blockIdx.x * blockDim.x + threadIdx.x) >> 5;
    int lane = threadIdx.x & 31;
    if (v >= V) return;
    const uint32_t* gi = (const uint32_t*)(gib + (long)v * 3 * GG);
    const uint32_t* gh = (const uint32_t*)(ghb + (long)v * 3 * GG);
    uint32_t* h = (uint32_t*)(hb + (long)v * GG);
    float s0 = 0.f, s1 = 0.f;
    #pragma unroll
    for (int k = 0; k < 4; k++) {
        int j2 = lane + 32 * k;
        if (j2 >= GG / 2) continue;
        float ir0, ir1, iz0, iz1, in0, in1, hr0, hr1, hz0, hz1, hn0, hn1, ho0, ho1;
        unpackbf(gi[j2], ir0, ir1);
        unpackbf(gi[j2 + 100], iz0, iz1);
        unpackbf(gi[j2 + 200], in0, in1);
        unpackbf(gh[j2], hr0, hr1);
        unpackbf(gh[j2 + 100], hz0, hz1);
        unpackbf(gh[j2 + 200], hn0, hn1);
        unpackbf(h[j2], ho0, ho1);
        float r0 = sigmoidf_(ir0 + hr0), r1 = sigmoidf_(ir1 + hr1);
        float z0 = sigmoidf_(iz0 + hz0), z1 = sigmoidf_(iz1 + hz1);
        float n0 = tanhf(in0 + r0 * hn0), n1 = tanhf(in1 + r1 * hn1);
        float o0 = (1.f - z0) * n0 + z0 * ho0;
        float o1 = (1.f - z1) * n1 + z1 * ho1;
        o0 = o0 > 0.f ? o0 : 0.f;
        o1 = o1 > 0.f ? o1 : 0.f;
        h[j2] = packbf(o0, o1);
        s0 += o0 * w0[2 * j2] + o1 * w0[2 * j2 + 1];
        if (mode == 0) s1 += o0 * w1[2 * j2] + o1 * w1[2 * j2 + 1];
    }
    s0 = warp_sum(s0);
    if (mode == 0) s1 = warp_sum(s1);
    if (lane == 0) {
        if (mode == 0) {
            d0[v] = s0;
            d1[v] = s1;
        } else {
            float ap = s0 + predb[0] + mask[v];
            out_atom[v] = ap;
            atomicAdd(&gsum[gids[v]], exp10f(-ap));
        }
    }
}

__global__ void final_kernel(const float* __restrict__ gsum, float* __restrict__ out, int NG) {
    int g = blockIdx.x * blockDim.x + threadIdx.x;
    if (g >= NG) return;
    out[g] = -log10f(gsum[g]);
}

// ---- host ----
static inline int cdiv(int a, int b) { return (a + b - 1) / b; }
#define GEMM_SMEM (GSTG * 2 * GTSZ * 4)

extern "C" void kernel_launch(void* const* d_in, const int* in_sizes, int n_in,
                              void* d_out, int out_size)
{
    const float* node_feats = (const float*)d_in[0];
    const float* edge_feats = (const float*)d_in[1];
    const float* pn_W  = (const float*)d_in[2];
    const float* pn_b  = (const float*)d_in[3];
    const float* pe1_W = (const float*)d_in[4];
    const float* pe1_b = (const float*)d_in[5];
    const float* pe2_W = (const float*)d_in[6];
    const float* pe2_b = (const float*)d_in[7];
    const float* et_W  = (const float*)d_in[8];
    const float* et_b  = (const float*)d_in[9];
    const float* gru0_Wih = (const float*)d_in[10];
    const float* gru0_Whh = (const float*)d_in[11];
    const float* gru0_bih = (const float*)d_in[12];
    const float* gru0_bhh = (const float*)d_in[13];
    const float* gnn_pe_W = (const float*)d_in[14];
    const float* gnn_pe_b = (const float*)d_in[15];
    const float* gnn_pn_W = (const float*)d_in[16];
    const float* gnn_pn_b = (const float*)d_in[17];
    const float* gnn_gru_Wih = (const float*)d_in[18];
    const float* gnn_gru_Whh = (const float*)d_in[19];
    const float* gnn_gru_bih = (const float*)d_in[20];
    const float* gnn_gru_bhh = (const float*)d_in[21];
    const float* pred_W = (const float*)d_in[22];
    const float* pred_b = (const float*)d_in[23];
    const int* srci = (const int*)d_in[24];
    const int* dsti = (const int*)d_in[25];
    const int* gids = (const int*)d_in[26];

    int V = in_sizes[0] / NFEAT;
    int E = in_sizes[24];
    int NG = out_size - V;
    float* out = (float*)d_out;
    int L = in_sizes[15];

    __nv_bfloat16 *hvb, *he1b, *cgb, *hvpb, *cb, *gib, *ghb;
    float *maskp, *d0, *d1, *logit, *gsum;
    uint32_t* wb;
    int *rowptr, *cursor, *csr;
    cudaGetSymbolAddress((void**)&hvb,   g_hvb);
    cudaGetSymbolAddress((void**)&he1b,  g_he1b);
    cudaGetSymbolAddress((void**)&cgb,   g_cgb);
    cudaGetSymbolAddress((void**)&hvpb,  g_hvpb);
    cudaGetSymbolAddress((void**)&cb,    g_cb);
    cudaGetSymbolAddress((void**)&gib,   g_gib);
    cudaGetSymbolAddress((void**)&ghb,   g_ghb);
    cudaGetSymbolAddress((void**)&wb,    g_wb);
    cudaGetSymbolAddress((void**)&maskp, g_mask);
    cudaGetSymbolAddress((void**)&d0,    g_d0);
    cudaGetSymbolAddress((void**)&d1,    g_d1);
    cudaGetSymbolAddress((void**)&logit, g_logit);
    cudaGetSymbolAddress((void**)&gsum,  g_gsum);
    cudaGetSymbolAddress((void**)&rowptr,g_rowptr);
    cudaGetSymbolAddress((void**)&cursor,g_cursor);
    cudaGetSymbolAddress((void**)&csr,   g_csr);

    cudaFuncSetAttribute(mma_bf16_kernel<0>, cudaFuncAttributeMaxDynamicSharedMemorySize, GEMM_SMEM);
    cudaFuncSetAttribute(mma_bf16_kernel<1>, cudaFuncAttributeMaxDynamicSharedMemorySize, GEMM_SMEM);

    dim3 blk(256);
    int warpgridV = cdiv(V * 32, 256);

    const int OFF_ET = 0;
    const int OFF_G0IH = 20000;
    const int OFF_G0HH = 80000;
    const int OFF_L0 = 140000;
    const int LSTRIDE = 140000;

    // ---- init + CSR build ----
    init_kernel<<<cdiv(E, 256), blk>>>(rowptr, V + 1, logit, E, gsum, NG,
                                       node_feats, maskp, V);
    hist_kernel<<<cdiv(E, 256), blk>>>(dsti, rowptr, E);
    scan_kernel<<<1, 1024>>>(rowptr, V + 1);
    copy_i_kernel<<<cdiv(V, 256), blk>>>(rowptr, cursor, V);
    csr_scatter_kernel<<<cdiv(E, 256), blk>>>(dsti, cursor, csr, E);

    // ---- launch 6: he1 GEMM with fused logit partial dot ----
    {
        dim3 g(cdiv(GG, BN), cdiv(E, BM));
        mma_smallk_kernel<2, 1><<<g, blk>>>(nullptr, 0, pe1_W, pe1_b, he1b,
                                            E, GG, NFEAT + NEFEAT, node_feats, edge_feats, srci,
                                            pe2_W + GG, logit);
    }
    // hvb = bf16(lrelu(node_feats @ pn_W + b))
    {
        dim3 g(cdiv(GG, BN), cdiv(V, BM));
        mma_smallk_kernel<0, 0><<<g, blk>>>(node_feats, NFEAT, pn_W, pn_b, hvb,
                                            V, GG, NFEAT, nullptr, nullptr, nullptr,
                                            nullptr, nullptr);
    }
    node_dots_kernel<<<warpgridV, blk>>>(hvb, pe2_W, d0, V);
    logit_fin_kernel<<<cdiv(E, 256), blk>>>(logit, d0, dsti, pe2_b, E);

    // ---- batched weight conversion ----
    {
        ConvJobs J = {};
        int nj = 0;
        J.W[nj] = et_W;     J.B[nj] = wb + OFF_ET;   J.K[nj] = 200; J.N[nj] = 200; nj++;
        J.W[nj] = gru0_Wih; J.B[nj] = wb + OFF_G0IH; J.K[nj] = 200; J.N[nj] = 600; nj++;
        J.W[nj] = gru0_Whh; J.B[nj] = wb + OFF_G0HH; J.K[nj] = 200; J.N[nj] = 600; nj++;
        for (int l = 0; l < L && nj + 3 <= 9; l++) {
            int base = OFF_L0 + l * LSTRIDE;
            J.W[nj] = gnn_pn_W + (long)l * 40000;      J.B[nj] = wb + base;         J.K[nj] = 200; J.N[nj] = 200; nj++;
            J.W[nj] = gnn_gru_Wih + (long)l * 120000;  J.B[nj] = wb + base + 20000; J.K[nj] = 200; J.N[nj] = 600; nj++;
            J.W[nj] = gnn_gru_Whh + (long)l * 120000;  J.B[nj] = wb + base + 80000; J.K[nj] = 200; J.N[nj] = 600; nj++;
        }
        J.njobs = nj;
        dim3 g(118, nj);
        convw_all_kernel<<<g, blk>>>(J);
    }

    // context: fused softmax+gather -> cgb; cb = elu(cgb @ et_W + et_b)
    att_gather_kernel<0><<<warpgridV, blk>>>(he1b, logit, nullptr, nullptr, nullptr, nullptr,
                                             rowptr, csr, cgb, V);
    {
        GemmJobs J = {};
        J.A[0] = cgb; J.Bt[0] = wb + OFF_ET; J.bias[0] = et_b; J.C[0] = cb;
        dim3 g(cdiv(GG, BN), cdiv(V, BM), 1);
        mma_bf16_kernel<1><<<g, dim3(128), GEMM_SMEM>>>(J, V, GG, GG);
    }
    // GRU0 gi+gh in one launch (z-batched)
    {
        GemmJobs J = {};
        J.A[0] = cb;  J.Bt[0] = wb + OFF_G0IH; J.bias[0] = gru0_bih; J.C[0] = gib;
        J.A[1] = hvb; J.Bt[1] = wb + OFF_G0HH; J.bias[1] = gru0_bhh; J.C[1] = ghb;
        dim3 g(cdiv(3 * GG, BN), cdiv(V, BM), 2);
        mma_bf16_kernel<0><<<g, dim3(128), GEMM_SMEM>>>(J, V, 3 * GG, GG);
    }
    if (L > 0)
        gru_gates_fused<<<warpgridV, blk>>>(gib, ghb, hvb, gnn_pe_W, gnn_pe_W + GG,
                                            d0, d1, nullptr, nullptr, nullptr, nullptr, nullptr, V, 0);
    else
        gru_gates_fused<<<warpgridV, blk>>>(gib, ghb, hvb, pred_W, nullptr, nullptr, nullptr,
                                            pred_b, maskp, gids, out + NG, gsum, V, 1);

    for (int l = 0; l < L; l++) {
        int base = OFF_L0 + l * LSTRIDE;
        {
            GemmJobs J = {};
            J.A[0] = hvb; J.Bt[0] = wb + base; J.bias[0] = gnn_pn_b + (long)l * GG; J.C[0] = hvpb;
            dim3 g(cdiv(GG, BN), cdiv(V, BM), 1);
            mma_bf16_kernel<0><<<g, dim3(128), GEMM_SMEM>>>(J, V, GG, GG);
        }
        att_gather_kernel<1><<<warpgridV, blk>>>(hvpb, nullptr, d0, d1, srci, gnn_pe_b + l,
                                                 rowptr, csr, cb, V);
        {
            GemmJobs J = {};
            J.A[0] = cb;  J.Bt[0] = wb + base + 20000; J.bias[0] = gnn_gru_bih + (long)l * 3 * GG; J.C[0] = gib;
            J.A[1] = hvb; J.Bt[1] = wb + base + 80000; J.bias[1] = gnn_gru_bhh + (long)l * 3 * GG; J.C[1] = ghb;
            dim3 g(cdiv(3 * GG, BN), cdiv(V, BM), 2);
            mma_bf16_kernel<0><<<g, dim3(128), GEMM_SMEM>>>(J, V, 3 * GG, GG);
        }
        if (l + 1 < L)
            gru_gates_fused<<<warpgridV, blk>>>(gib, ghb, hvb,
                                                gnn_pe_W + (long)(l + 1) * 2 * GG,
                                                gnn_pe_W + (long)(l + 1) * 2 * GG + GG,
                                                d0, d1, nullptr, nullptr, nullptr, nullptr, nullptr, V, 0);
        else
            gru_gates_fused<<<warpgridV, blk>>>(gib, ghb, hvb, pred_W, nullptr, nullptr, nullptr,
                                                pred_b, maskp, gids, out + NG, gsum, V, 1);
    }

    final_kernel<<<cdiv(NG, 256), blk>>>(gsum, out, NG);
}

// round 15
// speedup vs baseline: 1.1144x; 1.1144x over previous
#include <cuda_runtime.h>
#include <cuda_bf16.h>
#include <math.h>
#include <stdint.h>

// ---- problem constants ----
#define VV 100000
#define EE 400000
#define GG 200
#define NFEAT 74
#define NEFEAT 12

// ---- scratch (activations bf16) ----
__device__ __nv_bfloat16  g_hvb [VV * GG];
__device__ __nv_bfloat16  g_he1b[EE * GG];
__device__ __nv_bfloat16  g_cgb [VV * GG];
__device__ __nv_bfloat16  g_hvpb[VV * GG];
__device__ __nv_bfloat16  g_cb  [VV * GG];
__device__ __nv_bfloat16  g_gib [VV * 3 * GG];
__device__ __nv_bfloat16  g_ghb [VV * 3 * GG];
__device__ uint32_t       g_wb[430000];
__device__ float          g_mask[VV];
__device__ float          g_d0[VV];
__device__ float          g_d1[VV];
__device__ float          g_logit[EE];
__device__ float          g_gsum[8192];
__device__ int            g_rowptr[VV + 1];
__device__ int            g_cursor[VV];
__device__ int            g_csr[EE];

// ---- helpers ----
__device__ __forceinline__ float lreluf(float x) { return x > 0.f ? x : 0.01f * x; }
__device__ __forceinline__ float sigmoidf_(float x) { return 1.f / (1.f + expf(-x)); }
__device__ __forceinline__ float warp_sum(float v) {
    #pragma unroll
    for (int o = 16; o; o >>= 1) v += __shfl_down_sync(0xffffffffu, v, o);
    return v;
}
__device__ __forceinline__ float warp_allmax(float v) {
    #pragma unroll
    for (int o = 16; o; o >>= 1) v = fmaxf(v, __shfl_xor_sync(0xffffffffu, v, o));
    return v;
}
__device__ __forceinline__ uint32_t packbf(float lo, float hi) {
    __nv_bfloat162 p = __floats2bfloat162_rn(lo, hi);
    return *reinterpret_cast<uint32_t*>(&p);
}
__device__ __forceinline__ void unpackbf(uint32_t u, float& lo, float& hi) {
    __nv_bfloat162 p = *reinterpret_cast<__nv_bfloat162*>(&u);
    lo = __bfloat162float(p.x);
    hi = __bfloat162float(p.y);
}
__device__ __forceinline__ void cp_async16(uint32_t saddr, const void* g, int bytes) {
    asm volatile("cp.async.cg.shared.global [%0], [%1], 16, %2;"
                 :: "r"(saddr), "l"(g), "r"(bytes));
}
__device__ __forceinline__ void cp_commit() { asm volatile("cp.async.commit_group;"); }
template<int NN>
__device__ __forceinline__ void cp_wait() { asm volatile("cp.async.wait_group %0;" :: "n"(NN)); }

// ---- init: zero rowptr/logit/gsum/d0 + compute mask ----
__global__ void init_kernel(int* rowptr, int nrp, float* logit, int E,
                            float* gsum, int NG, float* d0,
                            const float* __restrict__ nf, float* __restrict__ mask, int V) {
    int i = blockIdx.x * blockDim.x + threadIdx.x;
    if (i < nrp) rowptr[i] = 0;
    if (i < E) logit[i] = 0.f;
    if (i < NG) gsum[i] = 0.f;
    if (i < V) {
        d0[i] = 0.f;
        const float* r = nf + (long)i * NFEAT;
        float s = r[NFEAT - 4] + r[NFEAT - 3] + r[NFEAT - 2] + r[NFEAT - 1];
        mask[i] = 1.f / (s * (1.f - r[0])) - 1.f;
    }
}

// ---- batched weight conversion ----
struct ConvJobs {
    const float* W[9];
    uint32_t* B[9];
    int K[9], N[9];
    int njobs;
};
__global__ void convw_all_kernel(ConvJobs J) {
    int j = blockIdx.y;
    if (j >= J.njobs) return;
    const float* W = J.W[j];
    uint32_t* Bt = J.B[j];
    int K = J.K[j], N = J.N[j];
    int K2 = K >> 1;
    int tot = N * K2;
    for (int idx = blockIdx.x * blockDim.x + threadIdx.x; idx < tot;
         idx += gridDim.x * blockDim.x) {
        int n = idx / K2, k2 = idx - n * K2;
        Bt[idx] = packbf(W[(long)(2 * k2) * N + n], W[(long)(2 * k2 + 1) * N + n]);
    }
}

// ---- CSR build ----
__global__ void hist_kernel(const int* __restrict__ dst, int* __restrict__ rowptr, int E) {
    int e = blockIdx.x * blockDim.x + threadIdx.x;
    if (e < E) atomicAdd(&rowptr[dst[e] + 1], 1);
}
__global__ void scan_kernel(int* __restrict__ p, int n) {
    __shared__ int tsum[1024];
    int tid = threadIdx.x;
    int chunk = (n + 1023) / 1024;
    int s0 = tid * chunk, s1 = min(s0 + chunk, n);
    int sum = 0;
    for (int i = s0; i < s1; i++) sum += p[i];
    tsum[tid] = sum;
    __syncthreads();
    int val = tsum[tid];
    #pragma unroll
    for (int o = 1; o < 1024; o <<= 1) {
        int other = (tid >= o) ? tsum[tid - o] : 0;
        __syncthreads();
        val += other;
        tsum[tid] = val;
        __syncthreads();
    }
    int offset = (tid > 0) ? tsum[tid - 1] : 0;
    int run = offset;
    for (int i = s0; i < s1; i++) { run += p[i]; p[i] = run; }
}
__global__ void copy_i_kernel(const int* __restrict__ a, int* __restrict__ b, int n) {
    int i = blockIdx.x * blockDim.x + threadIdx.x;
    if (i < n) b[i] = a[i];
}
__global__ void csr_scatter_kernel(const int* __restrict__ dst, int* __restrict__ cursor,
                                   int* __restrict__ csr, int E) {
    int e = blockIdx.x * blockDim.x + threadIdx.x;
    if (e >= E) return;
    int pos = atomicAdd(&cursor[dst[e]], 1);
    csr[pos] = e;
}

#define BM 128
#define BN 128
#define BK 32
#define SA 20
#define GSTG 3
#define GTSZ (128 * SA)

// ============================================================
// Streaming bf16 GEMM, occupancy 3. EPI: 0=store(+bias), 1=elu(+bias)
// ============================================================
template<int EPI>
__global__ __launch_bounds__(128, 3)
void mma_bf16_kernel(const __nv_bfloat16* __restrict__ A,
                     const uint32_t* __restrict__ Bt,
                     const float* __restrict__ bias,
                     __nv_bfloat16* __restrict__ C,
                     int M, int N, int K)
{
    extern __shared__ uint32_t smdyn[];
    uint32_t* Asm = smdyn;
    uint32_t* Bsm = smdyn + GSTG * GTSZ;

    const int tid = threadIdx.x;
    const int row0 = blockIdx.y * BM;
    const int col0 = blockIdx.x * BN;
    const int warp = tid >> 5, lane = tid & 31;
    const int wm = (warp & 1) * 64, wn = (warp >> 1) * 64;
    const int gq = lane >> 2, tq = lane & 3;
    const int K2 = K >> 1;
    const int nk = (K + BK - 1) / BK;

    const uint32_t sA0 = (uint32_t)__cvta_generic_to_shared(Asm);
    const uint32_t sB0 = (uint32_t)__cvta_generic_to_shared(Bsm);

    float acc[4][8][4] = {};

    auto issue = [&](int kt, int s) {
        int k2t = kt * 16;
        #pragma unroll
        for (int i = 0; i < 4; i++) {
            int idx = i * 128 + tid;
            int r = idx >> 2, seg = idx & 3;
            int k2g = k2t + seg * 4;
            {
                int gr = row0 + r;
                bool ok = (gr < M) && (k2g < K2);
                int bytes = ok ? min(16, (K2 - k2g) * 4) : 0;
                const void* gp = ok ? (const void*)(A + (long)gr * K + 2 * k2g)
                                    : (const void*)A;
                cp_async16(sA0 + (s * GTSZ + r * SA + seg * 4) * 4, gp, bytes);
            }
            {
                int gn = col0 + r;
                bool ok = (gn < N) && (k2g < K2);
                int bytes = ok ? min(16, (K2 - k2g) * 4) : 0;
                const void* gp = ok ? (const void*)(Bt + (long)gn * K2 + k2g)
                                    : (const void*)Bt;
                cp_async16(sB0 + (s * GTSZ + r * SA + seg * 4) * 4, gp, bytes);
            }
        }
        cp_commit();
    };

    const int rowA  = (lane & 7) + (lane & 8);
    const int kaddA = (lane & 16) >> 2;
    const int rowB  = (lane & 7) + ((lane & 16) >> 1);
    const int kaddB = (lane & 8) >> 1;

    auto compute = [&](int s) {
        #pragma unroll
        for (int ks = 0; ks < 2; ks++) {
            uint32_t af[4][4], bf[8][2];
            #pragma unroll
            for (int mt = 0; mt < 4; mt++) {
                uint32_t addr = sA0 + (s * GTSZ + (wm + mt * 16 + rowA) * SA + 8 * ks + kaddA) * 4;
                asm volatile("ldmatrix.sync.aligned.m8n8.x4.shared.b16 {%0,%1,%2,%3}, [%4];"
                    : "=r"(af[mt][0]), "=r"(af[mt][1]), "=r"(af[mt][2]), "=r"(af[mt][3])
                    : "r"(addr));
            }
            #pragma unroll
            for (int np = 0; np < 4; np++) {
                uint32_t addr = sB0 + (s * GTSZ + (wn + np * 16 + rowB) * SA + 8 * ks + kaddB) * 4;
                asm volatile("ldmatrix.sync.aligned.m8n8.x4.shared.b16 {%0,%1,%2,%3}, [%4];"
                    : "=r"(bf[2 * np][0]), "=r"(bf[2 * np][1]),
                      "=r"(bf[2 * np + 1][0]), "=r"(bf[2 * np + 1][1])
                    : "r"(addr));
            }
            #pragma unroll
            for (int mt = 0; mt < 4; mt++)
                #pragma unroll
                for (int nt = 0; nt < 8; nt++) {
                    asm volatile(
                        "mma.sync.aligned.m16n8k16.row.col.f32.bf16.bf16.f32 "
                        "{%0,%1,%2,%3},{%4,%5,%6,%7},{%8,%9},{%0,%1,%2,%3};"
                        : "+f"(acc[mt][nt][0]), "+f"(acc[mt][nt][1]),
                          "+f"(acc[mt][nt][2]), "+f"(acc[mt][nt][3])
                        : "r"(af[mt][0]), "r"(af[mt][1]), "r"(af[mt][2]), "r"(af[mt][3]),
                          "r"(bf[nt][0]), "r"(bf[nt][1]));
                }
        }
    };

    issue(0, 0);
    if (nk > 1) issue(1, 1);
    for (int kt = 0; kt < nk; kt++) {
        if (kt < nk - 1) cp_wait<1>(); else cp_wait<0>();
        __syncthreads();
        if (kt + 2 < nk) issue(kt + 2, (kt + 2) % GSTG);
        compute(kt % GSTG);
    }

    #pragma unroll
    for (int mt = 0; mt < 4; mt++) {
        int r0 = row0 + wm + mt * 16 + gq;
        int r1 = r0 + 8;
        #pragma unroll
        for (int nt = 0; nt < 8; nt++) {
            int cn = col0 + wn + nt * 8 + tq * 2;
            if (cn >= N) continue;
            float b0 = bias[cn], b1 = bias[cn + 1];
            float v00 = acc[mt][nt][0] + b0, v01 = acc[mt][nt][1] + b1;
            float v10 = acc[mt][nt][2] + b0, v11 = acc[mt][nt][3] + b1;
            if (EPI == 1) {
                v00 = v00 > 0.f ? v00 : expm1f(v00);
                v01 = v01 > 0.f ? v01 : expm1f(v01);
                v10 = v10 > 0.f ? v10 : expm1f(v10);
                v11 = v11 > 0.f ? v11 : expm1f(v11);
            }
            if (r0 < M) *(uint32_t*)&C[(long)r0 * N + cn] = packbf(v00, v01);
            if (r1 < M) *(uint32_t*)&C[(long)r1 * N + cn] = packbf(v10, v11);
        }
    }
}

// ============================================================
// Small-K GEMM (fp32 inputs), bf16 lrelu store.
// AM: 0=direct, 2=concat. LOGIT: atomicAdd dot(lrelu_row, wlog) into logit[row].
// ============================================================
#define SB2 20
template<int AM, int LOGIT>
__global__ __launch_bounds__(256, 2)
void mma_smallk_kernel(const float* __restrict__ A, int lda,
                       const float* __restrict__ B,
                       const float* __restrict__ bias,
                       __nv_bfloat16* __restrict__ Cb,
                       int M, int N, int K,
                       const float* __restrict__ nodef, const float* __restrict__ edgef,
                       const int* __restrict__ src,
                       const float* __restrict__ wlog, float* __restrict__ logit)
{
    __shared__ uint32_t As[2][BM * SA];
    __shared__ uint32_t Bs[2][BN * SB2];

    const int tid = threadIdx.x;
    const int row0 = blockIdx.y * BM;
    const int col0 = blockIdx.x * BN;
    const int warp = tid >> 5, lane = tid & 31;
    const int gq = lane >> 2, tq = lane & 3;
    const int wm = (warp & 1) * 64;
    const int wn = (warp >> 1) * 32;
    const int nk = (K + BK - 1) / BK;

    float acc[4][4][4] = {};
    uint32_t ra[8], rb[8];

    auto loadA = [&](int k0) {
        #pragma unroll
        for (int i = 0; i < 8; i++) {
            int e = i * 256 + tid;
            int r = e >> 4, k2 = e & 15;
            int gr = row0 + r, gk = k0 + 2 * k2;
            float v0 = 0.f, v1 = 0.f;
            if (gr < M && gk < K) {
                if (AM == 2) {
                    if (gk < NFEAT) {
                        int s = src[gr];
                        const float* p = &nodef[(long)s * NFEAT + gk];
                        v0 = p[0]; v1 = p[1];
                    } else {
                        const float* p = &edgef[(long)gr * NEFEAT + (gk - NFEAT)];
                        v0 = p[0]; v1 = p[1];
                    }
                } else {
                    const float2 p = *(const float2*)&A[(long)gr * lda + gk];
                    v0 = p.x; v1 = p.y;
                }
            }
            ra[i] = packbf(v0, v1);
        }
    };
    auto loadB = [&](int k0) {
        #pragma unroll
        for (int i = 0; i < 8; i++) {
            int e = i * 256 + tid;
            int k2 = e >> 7, n = e & 127;
            int gk = k0 + 2 * k2, gn = col0 + n;
            float v0 = 0.f, v1 = 0.f;
            if (gk < K && gn < N) {
                v0 = B[(long)gk * N + gn];
                v1 = B[(long)(gk + 1) * N + gn];
            }
            rb[i] = packbf(v0, v1);
        }
    };
    auto storeA = [&](int buf) {
        #pragma unroll
        for (int i = 0; i < 8; i++) {
            int e = i * 256 + tid;
            As[buf][(e >> 4) * SA + (e & 15)] = ra[i];
        }
    };
    auto storeB = [&](int buf) {
        #pragma unroll
        for (int i = 0; i < 8; i++) {
            int e = i * 256 + tid;
            Bs[buf][(e & 127) * SB2 + (e >> 7)] = rb[i];
        }
    };
    auto compute = [&](int buf) {
        #pragma unroll
        for (int ks = 0; ks < 2; ks++) {
            uint32_t af[4][4], bf[4][2];
            #pragma unroll
            for (int mt = 0; mt < 4; mt++) {
                int r = wm + mt * 16 + gq;
                int kb = ks * 8 + tq;
                af[mt][0] = As[buf][(r    ) * SA + kb    ];
                af[mt][1] = As[buf][(r + 8) * SA + kb    ];
                af[mt][2] = As[buf][(r    ) * SA + kb + 4];
                af[mt][3] = As[buf][(r + 8) * SA + kb + 4];
            }
            #pragma unroll
            for (int nt = 0; nt < 4; nt++) {
                int n = wn + nt * 8 + gq;
                int kb = ks * 8 + tq;
                bf[nt][0] = Bs[buf][n * SB2 + kb    ];
                bf[nt][1] = Bs[buf][n * SB2 + kb + 4];
            }
            #pragma unroll
            for (int mt = 0; mt < 4; mt++)
                #pragma unroll
                for (int nt = 0; nt < 4; nt++) {
                    asm volatile(
                        "mma.sync.aligned.m16n8k16.row.col.f32.bf16.bf16.f32 "
                        "{%0,%1,%2,%3},{%4,%5,%6,%7},{%8,%9},{%0,%1,%2,%3};"
                        : "+f"(acc[mt][nt][0]), "+f"(acc[mt][nt][1]),
                          "+f"(acc[mt][nt][2]), "+f"(acc[mt][nt][3])
                        : "r"(af[mt][0]), "r"(af[mt][1]), "r"(af[mt][2]), "r"(af[mt][3]),
                          "r"(bf[nt][0]), "r"(bf[nt][1]));
                }
        }
    };

    loadA(0); loadB(0);
    storeA(0); storeB(0);
    __syncthreads();
    for (int kt = 0; kt < nk; kt++) {
        int buf = kt & 1;
        if (kt + 1 < nk) { loadA((kt + 1) * BK); loadB((kt + 1) * BK); }
        compute(buf);
        if (kt + 1 < nk) {
            __syncthreads();
            storeA(buf ^ 1); storeB(buf ^ 1);
            __syncthreads();
        }
    }

    float rsum[4][2] = {};
    #pragma unroll
    for (int mt = 0; mt < 4; mt++) {
        int rr[2] = { row0 + wm + mt * 16 + gq, row0 + wm + mt * 16 + gq + 8 };
        #pragma unroll
        for (int nt = 0; nt < 4; nt++) {
            int cn = col0 + wn + nt * 8 + tq * 2;
            if (cn >= N) continue;
            float b0 = bias[cn], b1 = bias[cn + 1];
            float w0 = 0.f, w1 = 0.f;
            if (LOGIT) { w0 = wlog[cn]; w1 = wlog[cn + 1]; }
            #pragma unroll
            for (int h = 0; h < 2; h++) {
                if (rr[h] >= M) continue;
                float v0 = lreluf(acc[mt][nt][2 * h] + b0);
                float v1 = lreluf(acc[mt][nt][2 * h + 1] + b1);
                *(uint32_t*)&Cb[(long)rr[h] * N + cn] = packbf(v0, v1);
                if (LOGIT) rsum[mt][h] += v0 * w0 + v1 * w1;
            }
        }
    }
    if (LOGIT) {
        #pragma unroll
        for (int mt = 0; mt < 4; mt++) {
            #pragma unroll
            for (int h = 0; h < 2; h++) {
                float s = rsum[mt][h];
                s += __shfl_xor_sync(0xffffffffu, s, 1);
                s += __shfl_xor_sync(0xffffffffu, s, 2);
                int row = row0 + wm + mt * 16 + gq + 8 * h;
                if (tq == 0 && row < M) atomicAdd(&logit[row], s);
            }
        }
    }
}

// ---- finalize context logit ----
__global__ void logit_fin_kernel(float* __restrict__ logit, const float* __restrict__ d0,
                                 const int* __restrict__ dst, const float* __restrict__ b, int E)
{
    int e = blockIdx.x * blockDim.x + threadIdx.x;
    if (e >= E) return;
    logit[e] = lreluf(logit[e] + d0[dst[e]] + b[0]);
}

// ============================================================
// Fused attention softmax + gather (warp per node).
// ============================================================
template<int MODE>
__global__ void att_gather_kernel(const __nv_bfloat16* __restrict__ X,
                                  const float* __restrict__ logit,
                                  const float* __restrict__ d0, const float* __restrict__ d1,
                                  const int* __restrict__ srcmap, const float* __restrict__ b,
                                  const int* __restrict__ rowptr, const int* __restrict__ csr,
                                  __nv_bfloat16* __restrict__ outb, int V)
{
    int node = (blockIdx.x * blockDim.x + threadIdx.x) >> 5;
    int lane = threadIdx.x & 31;
    if (node >= V) return;
    int s0 = rowptr[node], s1 = rowptr[node + 1];
    uint32_t* cd = (uint32_t*)(outb + (long)node * GG);
    if (s0 == s1) {
        #pragma unroll
        for (int k = 0; k < 4; k++) {
            int j2 = lane + 32 * k;
            if (j2 < GG / 2) cd[j2] = 0u;
        }
        return;
    }
    float d0v = 0.f, bv = 0.f;
    if (MODE == 1) { d0v = d0[node]; bv = b[0]; }
    float m = -1e30f;
    for (int i = s0 + lane; i < s1; i += 32) {
        int e = csr[i];
        float l = (MODE == 1) ? lreluf(d0v + d1[srcmap[e]] + bv) : logit[e];
        m = fmaxf(m, l);
    }
    m = warp_allmax(m);
    float s = 0.f;
    float accx[4] = {0.f, 0.f, 0.f, 0.f};
    float accy[4] = {0.f, 0.f, 0.f, 0.f};
    for (int i = s0; i < s1; i++) {
        int e = csr[i];
        long row;
        float l;
        if (MODE == 1) {
            int sr = srcmap[e];
            l = lreluf(d0v + d1[sr] + bv);
            row = sr;
        } else {
            l = logit[e];
            row = e;
        }
        float w = expf(l - m);
        s += w;
        const uint32_t* x = (const uint32_t*)(X + row * GG);
        #pragma unroll
        for (int k = 0; k < 4; k++) {
            int j2 = lane + 32 * k;
            if (j2 < GG / 2) {
                float lo, hi; unpackbf(x[j2], lo, hi);
                accx[k] = fmaf(w, lo, accx[k]);
                accy[k] = fmaf(w, hi, accy[k]);
            }
        }
    }
    float inv = 1.f / s;
    #pragma unroll
    for (int k = 0; k < 4; k++) {
        int j2 = lane + 32 * k;
        if (j2 < GG / 2) {
            float lo = accx[k] * inv, hi = accy[k] * inv;
            if (MODE == 1) {
                lo = lo > 0.f ? lo : expm1f(lo);
                hi = hi > 0.f ? hi : expm1f(hi);
            }
            cd[j2] = packbf(lo, hi);
        }
    }
}

// ---- fused GRU gates + (next-layer dots | pKa readout) ----
__global__ void gru_gates_fused(const __nv_bfloat16* __restrict__ gib,
                                const __nv_bfloat16* __restrict__ ghb,
                                __nv_bfloat16* __restrict__ hb,
                                const float* __restrict__ w0, const float* __restrict__ w1,
                                float* __restrict__ d0, float* __restrict__ d1,
                                const float* __restrict__ predb, const float* __restrict__ mask,
                                const int* __restrict__ gids, float* __restrict__ out_atom,
                                float* __restrict__ gsum, int V, int mode)
{
    int v = (blockIdx.x * blockDim.x + threadIdx.x) >> 5;
    int lane = threadIdx.x & 31;
    if (v >= V) return;
    const uint32_t* gi = (const uint32_t*)(gib + (long)v * 3 * GG);
    const uint32_t* gh = (const uint32_t*)(ghb + (long)v * 3 * GG);
    uint32_t* h = (uint32_t*)(hb + (long)v * GG);
    float s0 = 0.f, s1 = 0.f;
    #pragma unroll
    for (int k = 0; k < 4; k++) {
        int j2 = lane + 32 * k;
        if (j2 >= GG / 2) continue;
        float ir0, ir1, iz0, iz1, in0, in1, hr0, hr1, hz0, hz1, hn0, hn1, ho0, ho1;
        unpackbf(gi[j2], ir0, ir1);
        unpackbf(gi[j2 + 100], iz0, iz1);
        unpackbf(gi[j2 + 200], in0, in1);
        unpackbf(gh[j2], hr0, hr1);
        unpackbf(gh[j2 + 100], hz0, hz1);
        unpackbf(gh[j2 + 200], hn0, hn1);
        unpackbf(h[j2], ho0, ho1);
        float r0 = sigmoidf_(ir0 + hr0), r1 = sigmoidf_(ir1 + hr1);
        float z0 = sigmoidf_(iz0 + hz0), z1 = sigmoidf_(iz1 + hz1);
        float n0 = tanhf(in0 + r0 * hn0), n1 = tanhf(in1 + r1 * hn1);
        float o0 = (1.f - z0) * n0 + z0 * ho0;
        float o1 = (1.f - z1) * n1 + z1 * ho1;
        o0 = o0 > 0.f ? o0 : 0.f;
        o1 = o1 > 0.f ? o1 : 0.f;
        h[j2] = packbf(o0, o1);
        s0 += o0 * w0[2 * j2] + o1 * w0[2 * j2 + 1];
        if (mode == 0) s1 += o0 * w1[2 * j2] + o1 * w1[2 * j2 + 1];
    }
    s0 = warp_sum(s0);
    if (mode == 0) s1 = warp_sum(s1);
    if (lane == 0) {
        if (mode == 0) {
            d0[v] = s0;
            d1[v] = s1;
        } else {
            float ap = s0 + predb[0] + mask[v];
            out_atom[v] = ap;
            atomicAdd(&gsum[gids[v]], exp10f(-ap));
        }
    }
}

__global__ void final_kernel(const float* __restrict__ gsum, float* __restrict__ out, int NG) {
    int g = blockIdx.x * blockDim.x + threadIdx.x;
    if (g >= NG) return;
    out[g] = -log10f(gsum[g]);
}

// ---- host ----
static inline int cdiv(int a, int b) { return (a + b - 1) / b; }
#define GEMM_SMEM (GSTG * 2 * GTSZ * 4)

extern "C" void kernel_launch(void* const* d_in, const int* in_sizes, int n_in,
                              void* d_out, int out_size)
{
    const float* node_feats = (const float*)d_in[0];
    const float* edge_feats = (const float*)d_in[1];
    const float* pn_W  = (const float*)d_in[2];
    const float* pn_b  = (const float*)d_in[3];
    const float* pe1_W = (const float*)d_in[4];
    const float* pe1_b = (const float*)d_in[5];
    const float* pe2_W = (const float*)d_in[6];
    const float* pe2_b = (const float*)d_in[7];
    const float* et_W  = (const float*)d_in[8];
    const float* et_b  = (const float*)d_in[9];
    const float* gru0_Wih = (const float*)d_in[10];
    const float* gru0_Whh = (const float*)d_in[11];
    const float* gru0_bih = (const float*)d_in[12];
    const float* gru0_bhh = (const float*)d_in[13];
    const float* gnn_pe_W = (const float*)d_in[14];
    const float* gnn_pe_b = (const float*)d_in[15];
    const float* gnn_pn_W = (const float*)d_in[16];
    const float* gnn_pn_b = (const float*)d_in[17];
    const float* gnn_gru_Wih = (const float*)d_in[18];
    const float* gnn_gru_Whh = (const float*)d_in[19];
    const float* gnn_gru_bih = (const float*)d_in[20];
    const float* gnn_gru_bhh = (const float*)d_in[21];
    const float* pred_W = (const float*)d_in[22];
    const float* pred_b = (const float*)d_in[23];
    const int* srci = (const int*)d_in[24];
    const int* dsti = (const int*)d_in[25];
    const int* gids = (const int*)d_in[26];

    int V = in_sizes[0] / NFEAT;
    int E = in_sizes[24];
    int NG = out_size - V;
    float* out = (float*)d_out;
    int L = in_sizes[15];

    __nv_bfloat16 *hvb, *he1b, *cgb, *hvpb, *cb, *gib, *ghb;
    float *maskp, *d0, *d1, *logit, *gsum;
    uint32_t* wb;
    int *rowptr, *cursor, *csr;
    cudaGetSymbolAddress((void**)&hvb,   g_hvb);
    cudaGetSymbolAddress((void**)&he1b,  g_he1b);
    cudaGetSymbolAddress((void**)&cgb,   g_cgb);
    cudaGetSymbolAddress((void**)&hvpb,  g_hvpb);
    cudaGetSymbolAddress((void**)&cb,    g_cb);
    cudaGetSymbolAddress((void**)&gib,   g_gib);
    cudaGetSymbolAddress((void**)&ghb,   g_ghb);
    cudaGetSymbolAddress((void**)&wb,    g_wb);
    cudaGetSymbolAddress((void**)&maskp, g_mask);
    cudaGetSymbolAddress((void**)&d0,    g_d0);
    cudaGetSymbolAddress((void**)&d1,    g_d1);
    cudaGetSymbolAddress((void**)&logit, g_logit);
    cudaGetSymbolAddress((void**)&gsum,  g_gsum);
    cudaGetSymbolAddress((void**)&rowptr,g_rowptr);
    cudaGetSymbolAddress((void**)&cursor,g_cursor);
    cudaGetSymbolAddress((void**)&csr,   g_csr);

    cudaFuncSetAttribute(mma_bf16_kernel<0>, cudaFuncAttributeMaxDynamicSharedMemorySize, GEMM_SMEM);
    cudaFuncSetAttribute(mma_bf16_kernel<1>, cudaFuncAttributeMaxDynamicSharedMemorySize, GEMM_SMEM);

    dim3 blk(256);
    int warpgridV = cdiv(V * 32, 256);

    const int OFF_ET = 0;
    const int OFF_G0IH = 20000;
    const int OFF_G0HH = 80000;
    const int OFF_L0 = 140000;
    const int LSTRIDE = 140000;

    // ---- init + CSR build ----
    init_kernel<<<cdiv(E, 256), blk>>>(rowptr, V + 1, logit, E, gsum, NG, d0,
                                       node_feats, maskp, V);
    hist_kernel<<<cdiv(E, 256), blk>>>(dsti, rowptr, E);
    scan_kernel<<<1, 1024>>>(rowptr, V + 1);
    copy_i_kernel<<<cdiv(V, 256), blk>>>(rowptr, cursor, V);
    csr_scatter_kernel<<<cdiv(E, 256), blk>>>(dsti, cursor, csr, E);

    // ---- launch 6: he1 GEMM with fused logit partial dot ----
    {
        dim3 g(cdiv(GG, BN), cdiv(E, BM));
        mma_smallk_kernel<2, 1><<<g, blk>>>(nullptr, 0, pe1_W, pe1_b, he1b,
                                            E, GG, NFEAT + NEFEAT, node_feats, edge_feats, srci,
                                            pe2_W + GG, logit);
    }
    // hvb GEMM with fused d0 dot (pe2_W first half) -- sole change vs R13
    {
        dim3 g(cdiv(GG, BN), cdiv(V, BM));
        mma_smallk_kernel<0, 1><<<g, blk>>>(node_feats, NFEAT, pn_W, pn_b, hvb,
                                            V, GG, NFEAT, nullptr, nullptr, nullptr,
                                            pe2_W, d0);
    }
    logit_fin_kernel<<<cdiv(E, 256), blk>>>(logit, d0, dsti, pe2_b, E);

    // ---- batched weight conversion ----
    {
        ConvJobs J = {};
        int nj = 0;
        J.W[nj] = et_W;     J.B[nj] = wb + OFF_ET;   J.K[nj] = 200; J.N[nj] = 200; nj++;
        J.W[nj] = gru0_Wih; J.B[nj] = wb + OFF_G0IH; J.K[nj] = 200; J.N[nj] = 600; nj++;
        J.W[nj] = gru0_Whh; J.B[nj] = wb + OFF_G0HH; J.K[nj] = 200; J.N[nj] = 600; nj++;
        for (int l = 0; l < L && nj + 3 <= 9; l++) {
            int base = OFF_L0 + l * LSTRIDE;
            J.W[nj] = gnn_pn_W + (long)l * 40000;      J.B[nj] = wb + base;         J.K[nj] = 200; J.N[nj] = 200; nj++;
            J.W[nj] = gnn_gru_Wih + (long)l * 120000;  J.B[nj] = wb + base + 20000; J.K[nj] = 200; J.N[nj] = 600; nj++;
            J.W[nj] = gnn_gru_Whh + (long)l * 120000;  J.B[nj] = wb + base + 80000; J.K[nj] = 200; J.N[nj] = 600; nj++;
        }
        J.njobs = nj;
        dim3 g(118, nj);
        convw_all_kernel<<<g, blk>>>(J);
    }

    // context: fused softmax+gather -> cgb; cb = elu(cgb @ et_W + et_b)
    att_gather_kernel<0><<<warpgridV, blk>>>(he1b, logit, nullptr, nullptr, nullptr, nullptr,
                                             rowptr, csr, cgb, V);
    {
        dim3 g(cdiv(GG, BN), cdiv(V, BM));
        mma_bf16_kernel<1><<<g, dim3(128), GEMM_SMEM>>>(cgb, wb + OFF_ET, et_b, cb, V, GG, GG);
    }
    // GRU0 (separate launches — z-batching regressed)
    {
        dim3 g(cdiv(3 * GG, BN), cdiv(V, BM));
        mma_bf16_kernel<0><<<g, dim3(128), GEMM_SMEM>>>(cb, wb + OFF_G0IH, gru0_bih, gib, V, 3 * GG, GG);
        mma_bf16_kernel<0><<<g, dim3(128), GEMM_SMEM>>>(hvb, wb + OFF_G0HH, gru0_bhh, ghb, V, 3 * GG, GG);
    }
    if (L > 0)
        gru_gates_fused<<<warpgridV, blk>>>(gib, ghb, hvb, gnn_pe_W, gnn_pe_W + GG,
                                            d0, d1, nullptr, nullptr, nullptr, nullptr, nullptr, V, 0);
    else
        gru_gates_fused<<<warpgridV, blk>>>(gib, ghb, hvb, pred_W, nullptr, nullptr, nullptr,
                                            pred_b, maskp, gids, out + NG, gsum, V, 1);

    for (int l = 0; l < L; l++) {
        int base = OFF_L0 + l * LSTRIDE;
        {
            dim3 g(cdiv(GG, BN), cdiv(V, BM));
            mma_bf16_kernel<0><<<g, dim3(128), GEMM_SMEM>>>(hvb, wb + base,
                                                            gnn_pn_b + (long)l * GG, hvpb, V, GG, GG);
        }
        att_gather_kernel<1><<<warpgridV, blk>>>(hvpb, nullptr, d0, d1, srci, gnn_pe_b + l,
                                                 rowptr, csr, cb, V);
        {
            dim3 g(cdiv(3 * GG, BN), cdiv(V, BM));
            mma_bf16_kernel<0><<<g, dim3(128), GEMM_SMEM>>>(cb, wb + base + 20000,
                                                            gnn_gru_bih + (long)l * 3 * GG, gib, V, 3 * GG, GG);
            mma_bf16_kernel<0><<<g, dim3(128), GEMM_SMEM>>>(hvb, wb + base + 80000,
                                                            gnn_gru_bhh + (long)l * 3 * GG, ghb, V, 3 * GG, GG);
        }
        if (l + 1 < L)
            gru_gates_fused<<<warpgridV, blk>>>(gib, ghb, hvb,
                                                gnn_pe_W + (long)(l + 1) * 2 * GG,
                                                gnn_pe_W + (long)(l + 1) * 2 * GG + GG,
                                                d0, d1, nullptr, nullptr, nullptr, nullptr, nullptr, V, 0);
        else
            gru_gates_fused<<<warpgridV, blk>>>(gib, ghb, hvb, pred_W, nullptr, nullptr, nullptr,
                                                pred_b, maskp, gids, out + NG, gsum, V, 1);
    }

    final_kernel<<<cdiv(NG, 256), blk>>>(gsum, out, NG);
}